// round 12
// baseline (speedup 1.0000x reference)
#include <cuda_runtime.h>
#include <cuda_fp16.h>
#include <cstdint>

#define NN 50000
#define EE 800000
#define NG 512
#define N4 (NN / 4)
#define NBLK 49

// ---------------- static device scratch ----------------
__device__ __half g_xh[NN * 256];         // x in fp16
__device__ __half g_bufh[NN * 256];       // GEMM outs (prescaled), td cols 0-127, bu 128-255
__device__ __half g_h1td[NN * 128];       // h1 td (post conv1, fp16)
__device__ __half g_h1bu[NN * 128];
__device__ __half g_wt1[256 * 256];       // W1^T fp16 [n][k]: n<128 td, n>=128 bu ; k=256
__device__ __half g_wt2[256 * 128];       // W2^T fp16 [n][k]: n<128 td, else bu ; k=128
__device__ float  g_pool[NG * 256];       // pooled concat fp32: bu @0, td @128
__device__ float  g_mlp[NG * 256];
__device__ int    g_deg[2 * NN];
__device__ float  g_dinv[2 * NN];
__device__ int    g_off_td[NN + 1];
__device__ int    g_off_bu[NN + 1];
__device__ int    g_cur_td[NN];
__device__ int    g_cur_bu[NN];
__device__ int    g_part[2 * NBLK];
__device__ int    g_csr_td[EE];
__device__ int    g_csr_bu[EE];

// ---------------- utility kernels ----------------
__global__ void zero_f4(float* p, int n4) {
    int i = blockIdx.x * blockDim.x + threadIdx.x;
    if (i < n4) ((float4*)p)[i] = make_float4(0.f, 0.f, 0.f, 0.f);
}
__global__ void zero_i(int* p, int n) {
    int i = blockIdx.x * blockDim.x + threadIdx.x;
    if (i < n) p[i] = 0;
}
__global__ void deg_kernel(const int* __restrict__ src, const int* __restrict__ dst,
                           int* deg_in, int* deg_out, int e) {
    int i = blockIdx.x * blockDim.x + threadIdx.x;
    if (i < e) {
        atomicAdd(&deg_in[dst[i]], 1);
        atomicAdd(&deg_out[src[i]], 1);
    }
}
__global__ void dinv_kernel(const int* __restrict__ deg, float* __restrict__ dinv, int n) {
    int i = blockIdx.x * blockDim.x + threadIdx.x;
    if (i < n) dinv[i] = rsqrtf((float)deg[i] + 1.0f);
}

// convert x (fp32) -> fp16, 8 elems/thread
__global__ void cvt_x(const float* __restrict__ x, __half* __restrict__ xh, int n8) {
    int i = blockIdx.x * blockDim.x + threadIdx.x;
    if (i >= n8) return;
    const float4* x4 = (const float4*)x;
    float4 a = x4[2 * i], b = x4[2 * i + 1];
    __half2 h0 = __floats2half2_rn(a.x, a.y);
    __half2 h1 = __floats2half2_rn(a.z, a.w);
    __half2 h2 = __floats2half2_rn(b.x, b.y);
    __half2 h3 = __floats2half2_rn(b.z, b.w);
    uint4 o;
    o.x = *(uint32_t*)&h0; o.y = *(uint32_t*)&h1;
    o.z = *(uint32_t*)&h2; o.w = *(uint32_t*)&h3;
    ((uint4*)xh)[i] = o;
}

// build transposed fp16 weights: wt1[n][k] (k=256), wt2[n][k] (k=128)
__global__ void cvt_w(const float* __restrict__ tdW1, const float* __restrict__ buW1,
                      const float* __restrict__ tdW2, const float* __restrict__ buW2,
                      __half* __restrict__ wt1, __half* __restrict__ wt2) {
    int i = blockIdx.x * blockDim.x + threadIdx.x;
    if (i < 256 * 256) {
        int n = i >> 8, k = i & 255;
        float v = (n < 128) ? tdW1[k * 128 + n] : buW1[k * 128 + (n - 128)];
        wt1[n * 256 + k] = __float2half_rn(v);
    } else if (i < 256 * 256 + 256 * 128) {
        int j = i - 256 * 256;
        int n = j >> 7, k = j & 127;
        float v = (n < 128) ? tdW2[k * 128 + n] : buW2[k * 128 + (n - 128)];
        wt2[n * 128 + k] = __float2half_rn(v);
    }
}

// ---------------- 3-phase parallel scan (validated) ----------------
__global__ void scan_bsum(const int* __restrict__ deg, int* __restrict__ part) {
    int dir = blockIdx.y, b = blockIdx.x, tid = threadIdx.x;
    const int4* d4 = (const int4*)(deg + dir * NN);
    int i4 = b * 256 + tid;
    int s = 0;
    if (i4 < N4) { int4 v = d4[i4]; s = v.x + v.y + v.z + v.w; }
#pragma unroll
    for (int d = 16; d > 0; d >>= 1) s += __shfl_down_sync(0xffffffffu, s, d);
    __shared__ int wt[8];
    if ((tid & 31) == 0) wt[tid >> 5] = s;
    __syncthreads();
    if (tid < 8) {
        int v = wt[tid];
#pragma unroll
        for (int d = 4; d > 0; d >>= 1) v += __shfl_down_sync(0xffu, v, d);
        if (tid == 0) part[dir * NBLK + b] = v;
    }
}
__global__ void scan_part(int* __restrict__ part, int* __restrict__ off_td,
                          int* __restrict__ off_bu) {
    int w = threadIdx.x >> 5, lane = threadIdx.x & 31;
    if (w >= 2) return;
    int* p = part + w * NBLK;
    int v0 = (lane < NBLK) ? p[lane] : 0;
    int v1 = (lane + 32 < NBLK) ? p[lane + 32] : 0;
    int s0 = v0;
#pragma unroll
    for (int d = 1; d < 32; d <<= 1) {
        int t = __shfl_up_sync(0xffffffffu, s0, d);
        if (lane >= d) s0 += t;
    }
    int tot0 = __shfl_sync(0xffffffffu, s0, 31);
    int s1 = v1;
#pragma unroll
    for (int d = 1; d < 32; d <<= 1) {
        int t = __shfl_up_sync(0xffffffffu, s1, d);
        if (lane >= d) s1 += t;
    }
    s1 += tot0;
    if (lane < NBLK) p[lane] = s0 - v0;
    if (lane + 32 < NBLK) p[lane + 32] = s1 - v1;
    int total = __shfl_sync(0xffffffffu, s1, 31);
    if (lane == 0) (w == 0 ? off_td : off_bu)[NN] = total;
}
__global__ void scan_write(const int* __restrict__ deg, const int* __restrict__ part,
                           int* __restrict__ off_td, int* __restrict__ off_bu,
                           int* __restrict__ cur_td, int* __restrict__ cur_bu) {
    int dir = blockIdx.y, b = blockIdx.x, tid = threadIdx.x;
    int lane = tid & 31, w = tid >> 5;
    const int4* d4 = (const int4*)(deg + dir * NN);
    int i4 = b * 256 + tid;
    int4 v = make_int4(0, 0, 0, 0);
    if (i4 < N4) v = d4[i4];
    int ts = v.x + v.y + v.z + v.w;
    int incl = ts;
#pragma unroll
    for (int d = 1; d < 32; d <<= 1) {
        int t = __shfl_up_sync(0xffffffffu, incl, d);
        if (lane >= d) incl += t;
    }
    __shared__ int wt[8];
    if (lane == 31) wt[w] = incl;
    __syncthreads();
    if (w == 0 && lane < 8) {
        int x = wt[lane];
        int sx = x;
#pragma unroll
        for (int d = 1; d < 8; d <<= 1) {
            int t = __shfl_up_sync(0xffu, sx, d);
            if (lane >= d) sx += t;
        }
        wt[lane] = sx - x;
    }
    __syncthreads();
    int base = part[dir * NBLK + b] + wt[w] + (incl - ts);
    int* off = dir ? off_bu : off_td;
    int* cur = dir ? cur_bu : cur_td;
    if (i4 < N4) {
        int4 o;
        o.x = base;
        o.y = base + v.x;
        o.z = o.y + v.y;
        o.w = o.z + v.z;
        ((int4*)off)[i4] = o;
        ((int4*)cur)[i4] = o;
    }
}
__global__ void scatter_kernel(const int* __restrict__ src, const int* __restrict__ dst,
                               int* cur_td, int* cur_bu,
                               int* __restrict__ csr_td, int* __restrict__ csr_bu, int e) {
    int i = blockIdx.x * blockDim.x + threadIdx.x;
    if (i < e) {
        int s = src[i], d = dst[i];
        csr_td[atomicAdd(&cur_td[d], 1)] = s;
        csr_bu[atomicAdd(&cur_bu[s], 1)] = d;
    }
}

// ---------------- fp16 pipelined GEMM (cp.async, BK=32, double-buffered) ----------
#define AH_HALVES (128 * 40)
__global__ __launch_bounds__(256, 2)
void gemm_h(const __half* __restrict__ A0, const __half* __restrict__ A1,
            const __half* __restrict__ B0, const __half* __restrict__ B1,
            const float* __restrict__ rs0, const float* __restrict__ rs1,
            __half* __restrict__ C0, __half* __restrict__ C1,
            int M, int K, int lda, int ldc) {
    __shared__ __align__(16) __half As[2][AH_HALVES];
    __shared__ __align__(16) __half Bs[2][AH_HALVES];

    const __half* A = blockIdx.y ? A1 : A0;
    const __half* B = blockIdx.y ? B1 : B0;
    const float* rowscale = blockIdx.y ? rs1 : rs0;
    __half* C = blockIdx.y ? C1 : C0;

    const int tid = threadIdx.x;
    const int lane = tid & 31;
    const int warp = tid >> 5;
    const int g = lane >> 2, tig = lane & 3;
    const int m0 = blockIdx.x * 128;
    const int wm = (warp & 1) * 64, wn = (warp >> 1) * 32;

    const uint32_t sA = (uint32_t)__cvta_generic_to_shared(&As[0][0]);
    const uint32_t sB = (uint32_t)__cvta_generic_to_shared(&Bs[0][0]);

    float acc[4][4][4];
#pragma unroll
    for (int i = 0; i < 4; i++)
#pragma unroll
        for (int j = 0; j < 4; j++)
#pragma unroll
            for (int c = 0; c < 4; c++) acc[i][j][c] = 0.f;

    const int T = K >> 5;

#define ISSUEH(t)                                                                   \
    {                                                                               \
        const int k0 = (t) * 32;                                                    \
        const uint32_t ab = sA + (uint32_t)(((t) & 1) * AH_HALVES * 2);             \
        const uint32_t bb = sB + (uint32_t)(((t) & 1) * AH_HALVES * 2);             \
        _Pragma("unroll")                                                           \
        for (int l = 0; l < 2; l++) {                                               \
            int idx = tid + l * 256;                                                \
            int row = idx >> 2, ck = idx & 3;                                       \
            int gm = m0 + row;                                                      \
            const __half* srcp = A + (size_t)(gm < M ? gm : 0) * lda + k0 + ck * 8; \
            uint32_t dstp = ab + (uint32_t)(row * 80 + ck * 16);                    \
            int sz = gm < M ? 16 : 0;                                               \
            asm volatile("cp.async.cg.shared.global [%0], [%1], 16, %2;"            \
                         :: "r"(dstp), "l"(srcp), "r"(sz));                         \
        }                                                                           \
        _Pragma("unroll")                                                           \
        for (int l = 0; l < 2; l++) {                                               \
            int idx = tid + l * 256;                                                \
            int nr = idx >> 2, ck = idx & 3;                                        \
            const __half* srcp = B + (size_t)nr * K + k0 + ck * 8;                  \
            uint32_t dstp = bb + (uint32_t)(nr * 80 + ck * 16);                     \
            asm volatile("cp.async.cg.shared.global [%0], [%1], 16;"                \
                         :: "r"(dstp), "l"(srcp));                                  \
        }                                                                           \
        asm volatile("cp.async.commit_group;");                                     \
    }

    ISSUEH(0);
    for (int t = 0; t < T; t++) {
        if (t + 1 < T) {
            ISSUEH(t + 1);
            asm volatile("cp.async.wait_group 1;");
        } else {
            asm volatile("cp.async.wait_group 0;");
        }
        __syncthreads();
        const uint32_t* Aw = (const uint32_t*)&As[t & 1][0];
        const uint32_t* Bw = (const uint32_t*)&Bs[t & 1][0];
#pragma unroll
        for (int kk = 0; kk < 32; kk += 16) {
            const int kw = kk >> 1;
            uint32_t af[4][4], bf[4][2];
#pragma unroll
            for (int i = 0; i < 4; i++) {
                int mb = wm + i * 16 + g;
                af[i][0] = Aw[mb * 20 + kw + tig];
                af[i][1] = Aw[(mb + 8) * 20 + kw + tig];
                af[i][2] = Aw[mb * 20 + kw + 4 + tig];
                af[i][3] = Aw[(mb + 8) * 20 + kw + 4 + tig];
            }
#pragma unroll
            for (int j = 0; j < 4; j++) {
                int nb = wn + j * 8 + g;
                bf[j][0] = Bw[nb * 20 + kw + tig];
                bf[j][1] = Bw[nb * 20 + kw + 4 + tig];
            }
#pragma unroll
            for (int i = 0; i < 4; i++)
#pragma unroll
                for (int j = 0; j < 4; j++) {
                    asm volatile(
                        "mma.sync.aligned.m16n8k16.row.col.f32.f16.f16.f32 "
                        "{%0,%1,%2,%3}, {%4,%5,%6,%7}, {%8,%9}, {%0,%1,%2,%3};"
                        : "+f"(acc[i][j][0]), "+f"(acc[i][j][1]),
                          "+f"(acc[i][j][2]), "+f"(acc[i][j][3])
                        : "r"(af[i][0]), "r"(af[i][1]), "r"(af[i][2]), "r"(af[i][3]),
                          "r"(bf[j][0]), "r"(bf[j][1]));
                }
        }
        __syncthreads();
    }
#undef ISSUEH

#pragma unroll
    for (int i = 0; i < 4; i++) {
        int r0 = m0 + wm + i * 16 + g;
        int r1 = r0 + 8;
        float s0 = (r0 < M) ? rowscale[r0] : 1.f;
        float s1 = (r1 < M) ? rowscale[r1] : 1.f;
#pragma unroll
        for (int j = 0; j < 4; j++) {
            int cb = wn + j * 8 + 2 * tig;
            if (r0 < M) {
                __half2 p = __floats2half2_rn(acc[i][j][0] * s0, acc[i][j][1] * s0);
                *(__half2*)(C + (size_t)r0 * ldc + cb) = p;
            }
            if (r1 < M) {
                __half2 p = __floats2half2_rn(acc[i][j][2] * s1, acc[i][j][3] * s1);
                *(__half2*)(C + (size_t)r1 * ldc + cb) = p;
            }
        }
    }
}

// ---------------- small TF32 GEMM for MLP head (proven) ----------------
__device__ __forceinline__ uint32_t f2tf(float x) {
    uint32_t r;
    asm("cvt.rna.tf32.f32 %0, %1;" : "=r"(r) : "f"(x));
    return r;
}
__global__ __launch_bounds__(256, 2)
void gemm_tf32(const float* __restrict__ A, const float* __restrict__ B,
               const float* __restrict__ bias, float* __restrict__ C,
               int M, int K, int ldb, int ldc, int relu) {
    __shared__ uint32_t As[32][136];
    __shared__ uint32_t Bs[32][136];

    const int tid = threadIdx.x;
    const int lane = tid & 31;
    const int warp = tid >> 5;
    const int g = lane >> 2, tig = lane & 3;
    const int m0 = blockIdx.x * 128, n0 = blockIdx.y * 128;
    const int wm = (warp & 1) * 64, wn = (warp >> 1) * 32;

    float acc[4][4][4];
#pragma unroll
    for (int i = 0; i < 4; i++)
#pragma unroll
        for (int j = 0; j < 4; j++)
#pragma unroll
            for (int c = 0; c < 4; c++) acc[i][j][c] = 0.f;

    for (int k0 = 0; k0 < K; k0 += 32) {
#pragma unroll
        for (int r = 0; r < 4; r++) {
            int m = lane + 32 * r;
            int gm = m0 + m;
            float4 v = make_float4(0.f, 0.f, 0.f, 0.f);
            if (gm < M) v = *(const float4*)(A + (size_t)gm * K + k0 + warp * 4);
            As[warp * 4 + 0][m] = f2tf(v.x);
            As[warp * 4 + 1][m] = f2tf(v.y);
            As[warp * 4 + 2][m] = f2tf(v.z);
            As[warp * 4 + 3][m] = f2tf(v.w);
        }
#pragma unroll
        for (int l = 0; l < 4; l++) {
            int idx = tid + l * 256;
            int k = idx >> 5, nf = idx & 31;
            float4 v = *(const float4*)(B + (size_t)(k0 + k) * ldb + n0 + nf * 4);
            uint32_t* p = &Bs[k][nf * 4];
            p[0] = f2tf(v.x); p[1] = f2tf(v.y); p[2] = f2tf(v.z); p[3] = f2tf(v.w);
        }
        __syncthreads();
#pragma unroll
        for (int kk = 0; kk < 32; kk += 8) {
            uint32_t af[4][4], bf[4][2];
#pragma unroll
            for (int i = 0; i < 4; i++) {
                int mb = wm + i * 16 + g;
                af[i][0] = As[kk + tig][mb];
                af[i][1] = As[kk + tig][mb + 8];
                af[i][2] = As[kk + tig + 4][mb];
                af[i][3] = As[kk + tig + 4][mb + 8];
            }
#pragma unroll
            for (int j = 0; j < 4; j++) {
                int nb = wn + j * 8 + g;
                bf[j][0] = Bs[kk + tig][nb];
                bf[j][1] = Bs[kk + tig + 4][nb];
            }
#pragma unroll
            for (int i = 0; i < 4; i++)
#pragma unroll
                for (int j = 0; j < 4; j++) {
                    asm volatile(
                        "mma.sync.aligned.m16n8k8.row.col.f32.tf32.tf32.f32 "
                        "{%0,%1,%2,%3}, {%4,%5,%6,%7}, {%8,%9}, {%0,%1,%2,%3};"
                        : "+f"(acc[i][j][0]), "+f"(acc[i][j][1]),
                          "+f"(acc[i][j][2]), "+f"(acc[i][j][3])
                        : "r"(af[i][0]), "r"(af[i][1]), "r"(af[i][2]), "r"(af[i][3]),
                          "r"(bf[j][0]), "r"(bf[j][1]));
                }
        }
        __syncthreads();
    }

#pragma unroll
    for (int i = 0; i < 4; i++) {
        int r0 = m0 + wm + i * 16 + g;
        int r1 = r0 + 8;
#pragma unroll
        for (int j = 0; j < 4; j++) {
            int cb = n0 + wn + j * 8 + 2 * tig;
            float b0 = 0.f, b1 = 0.f;
            if (bias) { b0 = bias[cb]; b1 = bias[cb + 1]; }
            float v0 = acc[i][j][0] + b0, v1 = acc[i][j][1] + b1;
            float v2 = acc[i][j][2] + b0, v3 = acc[i][j][3] + b1;
            if (relu) {
                v0 = fmaxf(v0, 0.f); v1 = fmaxf(v1, 0.f);
                v2 = fmaxf(v2, 0.f); v3 = fmaxf(v3, 0.f);
            }
            if (r0 < M) *(float2*)(C + (size_t)r0 * ldc + cb) = make_float2(v0, v1);
            if (r1 < M) *(float2*)(C + (size_t)r1 * ldc + cb) = make_float2(v2, v3);
        }
    }
}

// ---------------- dual CSR aggregation v2: 2 warps/node, unroll-4 prefetch --------
// h prescaled by dinv. out = act( dinv[d]*(Σ h'[s] + h'[d]) + b )
// Each warp handles 64 halves (lane -> 2 halves). grid: (ceil(2*NN/8), 2).
__global__ void agg_dual_h2(const __half* __restrict__ h,
                            const int* __restrict__ csr0, const int* __restrict__ csr1,
                            const int* __restrict__ off0, const int* __restrict__ off1,
                            const float* __restrict__ dv0, const float* __restrict__ dv1,
                            const float* __restrict__ b0, const float* __restrict__ b1,
                            __half* __restrict__ out0, __half* __restrict__ out1, int relu,
                            const int* __restrict__ batch, float* __restrict__ pool) {
    const int y = blockIdx.y;
    const int* csr = y ? csr1 : csr0;
    const int* off = y ? off1 : off0;
    const float* dinv = y ? dv1 : dv0;
    const float* bias = y ? b1 : b0;
    __half* out = y ? out1 : out0;

    int gw = blockIdx.x * 8 + (threadIdx.x >> 5);
    int node = gw >> 1;
    if (node >= NN) return;
    int lane = threadIdx.x & 31;
    int col = (gw & 1) * 64 + lane * 2;            // feature index (0..126, even)
    const __half* hp = h + y * 128 + col;          // + s*256 per row

    int e0 = off[node], e1 = off[node + 1];
    float accx = 0.f, accy = 0.f;
    int j = e0;
    for (; j + 4 <= e1; j += 4) {
        int s0 = csr[j], s1 = csr[j + 1], s2 = csr[j + 2], s3 = csr[j + 3];
        uint32_t v0 = *(const uint32_t*)(hp + (size_t)s0 * 256);
        uint32_t v1 = *(const uint32_t*)(hp + (size_t)s1 * 256);
        uint32_t v2 = *(const uint32_t*)(hp + (size_t)s2 * 256);
        uint32_t v3 = *(const uint32_t*)(hp + (size_t)s3 * 256);
        float2 f0 = __half22float2(*(__half2*)&v0);
        float2 f1 = __half22float2(*(__half2*)&v1);
        float2 f2 = __half22float2(*(__half2*)&v2);
        float2 f3 = __half22float2(*(__half2*)&v3);
        accx += (f0.x + f1.x) + (f2.x + f3.x);
        accy += (f0.y + f1.y) + (f2.y + f3.y);
    }
    for (; j < e1; j++) {
        int s = csr[j];
        uint32_t v = *(const uint32_t*)(hp + (size_t)s * 256);
        float2 f = __half22float2(*(__half2*)&v);
        accx += f.x; accy += f.y;
    }
    float di = dinv[node];
    uint32_t sv = *(const uint32_t*)(hp + (size_t)node * 256);
    float2 sf = __half22float2(*(__half2*)&sv);
    float2 bv = *(const float2*)(bias + col);
    float rx = fmaf(di, accx + sf.x, bv.x);
    float ry = fmaf(di, accy + sf.y, bv.y);
    if (relu) { rx = fmaxf(rx, 0.f); ry = fmaxf(ry, 0.f); }
    if (pool) {
        int gi = batch[node];
        int po = y ? 0 : 128;                       // td -> [128,256), bu -> [0,128)
        float* p = pool + (size_t)gi * 256 + po + col;
        atomicAdd(p + 0, rx);
        atomicAdd(p + 1, ry);
    } else {
        __half2 o = __floats2half2_rn(rx, ry);
        *(__half2*)(out + (size_t)node * 128 + col) = o;
    }
}

// ---------------- launch ----------------
extern "C" void kernel_launch(void* const* d_in, const int* in_sizes, int n_in,
                              void* d_out, int out_size) {
    const float* x     = (const float*)d_in[0];
    const int*   ei    = (const int*)d_in[1];
    const int*   batch = (const int*)d_in[2];
    const float* td_W1 = (const float*)d_in[4];
    const float* td_b1 = (const float*)d_in[5];
    const float* td_W2 = (const float*)d_in[6];
    const float* td_b2 = (const float*)d_in[7];
    const float* bu_W1 = (const float*)d_in[8];
    const float* bu_b1 = (const float*)d_in[9];
    const float* bu_W2 = (const float*)d_in[10];
    const float* bu_b2 = (const float*)d_in[11];
    const float* pw1   = (const float*)d_in[12];
    const float* pb1   = (const float*)d_in[13];
    const float* pw2   = (const float*)d_in[14];
    const float* pb2   = (const float*)d_in[15];
    float* out = (float*)d_out;

    __half *xh, *bufh, *h1td, *h1bu, *wt1, *wt2;
    float *pool, *mlp, *dinv;
    int *deg, *off_td, *off_bu, *cur_td, *cur_bu, *part, *csr_td, *csr_bu;
    cudaGetSymbolAddress((void**)&xh,     g_xh);
    cudaGetSymbolAddress((void**)&bufh,   g_bufh);
    cudaGetSymbolAddress((void**)&h1td,   g_h1td);
    cudaGetSymbolAddress((void**)&h1bu,   g_h1bu);
    cudaGetSymbolAddress((void**)&wt1,    g_wt1);
    cudaGetSymbolAddress((void**)&wt2,    g_wt2);
    cudaGetSymbolAddress((void**)&pool,   g_pool);
    cudaGetSymbolAddress((void**)&mlp,    g_mlp);
    cudaGetSymbolAddress((void**)&dinv,   g_dinv);
    cudaGetSymbolAddress((void**)&deg,    g_deg);
    cudaGetSymbolAddress((void**)&off_td, g_off_td);
    cudaGetSymbolAddress((void**)&off_bu, g_off_bu);
    cudaGetSymbolAddress((void**)&cur_td, g_cur_td);
    cudaGetSymbolAddress((void**)&cur_bu, g_cur_bu);
    cudaGetSymbolAddress((void**)&part,   g_part);
    cudaGetSymbolAddress((void**)&csr_td, g_csr_td);
    cudaGetSymbolAddress((void**)&csr_bu, g_csr_bu);

    const int* src = ei;
    const int* dst = ei + EE;
    const float* dinv_td = dinv;
    const float* dinv_bu = dinv + NN;

    // --- graph structure ---
    zero_i<<<(2 * NN + 255) / 256, 256>>>(deg, 2 * NN);
    deg_kernel<<<(EE + 255) / 256, 256>>>(src, dst, deg, deg + NN, EE);
    dinv_kernel<<<(2 * NN + 255) / 256, 256>>>(deg, dinv, 2 * NN);
    scan_bsum<<<dim3(NBLK, 2), 256>>>(deg, part);
    scan_part<<<1, 64>>>(part, off_td, off_bu);
    scan_write<<<dim3(NBLK, 2), 256>>>(deg, part, off_td, off_bu, cur_td, cur_bu);
    scatter_kernel<<<(EE + 255) / 256, 256>>>(src, dst, cur_td, cur_bu, csr_td, csr_bu, EE);

    // --- converts + pool zero ---
    cvt_x<<<(NN * 32 + 255) / 256, 256>>>(x, xh, NN * 32);
    cvt_w<<<(256 * 256 + 256 * 128 + 255) / 256, 256>>>(td_W1, bu_W1, td_W2, bu_W2, wt1, wt2);
    zero_f4<<<(NG * 64 + 255) / 256, 256>>>(pool, NG * 64);

    const int gx = (NN + 127) / 128;                 // 391
    const int aggBlocks = (2 * NN + 7) / 8;          // 2 warps/node, 8 warps/block

    // conv1 GEMM (both branches): bufh = (xh @ W1^T) * dinv
    gemm_h<<<dim3(gx, 2), 256>>>(xh, xh, wt1, wt1 + 128 * 256, dinv_td, dinv_bu,
                                 bufh, bufh + 128, NN, 256, 256, 256);

    // conv1 aggregation + bias + relu -> h1 (fp16)
    agg_dual_h2<<<dim3(aggBlocks, 2), 256>>>(bufh, csr_td, csr_bu, off_td, off_bu,
                                             dinv_td, dinv_bu, td_b1, bu_b1,
                                             h1td, h1bu, 1, nullptr, nullptr);

    // conv2 GEMMs (both branches, prescaled)
    gemm_h<<<dim3(gx, 2), 256>>>(h1td, h1bu, wt2, wt2 + 128 * 128, dinv_td, dinv_bu,
                                 bufh, bufh + 128, NN, 128, 128, 256);

    // conv2 aggregation + bias, pooled into concat buffer [bu | td] (fp32)
    agg_dual_h2<<<dim3(aggBlocks, 2), 256>>>(bufh, csr_td, csr_bu, off_td, off_bu,
                                             dinv_td, dinv_bu, td_b2, bu_b2,
                                             nullptr, nullptr, 0, batch, pool);

    // MLP head (fp32 tf32 path)
    gemm_tf32<<<dim3(4, 2), 256>>>(pool, pw1, pb1, mlp, NG, 256, 256, 256, 1);
    gemm_tf32<<<dim3(4, 1), 256>>>(mlp,  pw2, pb2, out, NG, 256, 128, 128, 0);
}

// round 13
// speedup vs baseline: 1.1227x; 1.1227x over previous
#include <cuda_runtime.h>
#include <cuda_fp16.h>
#include <cstdint>

#define NN 50000
#define EE 800000
#define NG 512
#define N4 (NN / 4)
#define NBLK 49

// ---------------- static device scratch ----------------
__device__ __half g_xh[NN * 256];         // x in fp16
__device__ __half g_bufh[NN * 256];       // GEMM outs (prescaled), td cols 0-127, bu 128-255
__device__ __half g_h1td[NN * 128];       // h1 td (post conv1, fp16)
__device__ __half g_h1bu[NN * 128];
__device__ __half g_wt1[256 * 256];       // W1^T fp16 [n][k]: n<128 td, n>=128 bu ; k=256
__device__ __half g_wt2[256 * 128];       // W2^T fp16 [n][k]: n<128 td, else bu ; k=128
__device__ float  g_pool[NG * 256];       // pooled concat fp32: bu @0, td @128
__device__ float  g_mlp[NG * 256];
__device__ int    g_deg[2 * NN];
__device__ float  g_dinv[2 * NN];
__device__ int    g_off_td[NN + 1];
__device__ int    g_off_bu[NN + 1];
__device__ int    g_cur_td[NN];
__device__ int    g_cur_bu[NN];
__device__ int    g_part[2 * NBLK];
__device__ int    g_csr_td[EE];
__device__ int    g_csr_bu[EE];

// ---------------- utility kernels ----------------
__global__ void zero_f4(float* p, int n4) {
    int i = blockIdx.x * blockDim.x + threadIdx.x;
    if (i < n4) ((float4*)p)[i] = make_float4(0.f, 0.f, 0.f, 0.f);
}
__global__ void zero_i(int* p, int n) {
    int i = blockIdx.x * blockDim.x + threadIdx.x;
    if (i < n) p[i] = 0;
}
__global__ void deg_kernel(const int* __restrict__ src, const int* __restrict__ dst,
                           int* deg_in, int* deg_out, int e) {
    int i = blockIdx.x * blockDim.x + threadIdx.x;
    if (i < e) {
        atomicAdd(&deg_in[dst[i]], 1);
        atomicAdd(&deg_out[src[i]], 1);
    }
}
__global__ void dinv_kernel(const int* __restrict__ deg, float* __restrict__ dinv, int n) {
    int i = blockIdx.x * blockDim.x + threadIdx.x;
    if (i < n) dinv[i] = rsqrtf((float)deg[i] + 1.0f);
}

// convert x (fp32) -> fp16, 8 elems/thread
__global__ void cvt_x(const float* __restrict__ x, __half* __restrict__ xh, int n8) {
    int i = blockIdx.x * blockDim.x + threadIdx.x;
    if (i >= n8) return;
    const float4* x4 = (const float4*)x;
    float4 a = x4[2 * i], b = x4[2 * i + 1];
    __half2 h0 = __floats2half2_rn(a.x, a.y);
    __half2 h1 = __floats2half2_rn(a.z, a.w);
    __half2 h2 = __floats2half2_rn(b.x, b.y);
    __half2 h3 = __floats2half2_rn(b.z, b.w);
    uint4 o;
    o.x = *(uint32_t*)&h0; o.y = *(uint32_t*)&h1;
    o.z = *(uint32_t*)&h2; o.w = *(uint32_t*)&h3;
    ((uint4*)xh)[i] = o;
}

// build transposed fp16 weights: wt1[n][k] (k=256), wt2[n][k] (k=128)
__global__ void cvt_w(const float* __restrict__ tdW1, const float* __restrict__ buW1,
                      const float* __restrict__ tdW2, const float* __restrict__ buW2,
                      __half* __restrict__ wt1, __half* __restrict__ wt2) {
    int i = blockIdx.x * blockDim.x + threadIdx.x;
    if (i < 256 * 256) {
        int n = i >> 8, k = i & 255;
        float v = (n < 128) ? tdW1[k * 128 + n] : buW1[k * 128 + (n - 128)];
        wt1[n * 256 + k] = __float2half_rn(v);
    } else if (i < 256 * 256 + 256 * 128) {
        int j = i - 256 * 256;
        int n = j >> 7, k = j & 127;
        float v = (n < 128) ? tdW2[k * 128 + n] : buW2[k * 128 + (n - 128)];
        wt2[n * 128 + k] = __float2half_rn(v);
    }
}

// ---------------- 3-phase parallel scan (validated) ----------------
__global__ void scan_bsum(const int* __restrict__ deg, int* __restrict__ part) {
    int dir = blockIdx.y, b = blockIdx.x, tid = threadIdx.x;
    const int4* d4 = (const int4*)(deg + dir * NN);
    int i4 = b * 256 + tid;
    int s = 0;
    if (i4 < N4) { int4 v = d4[i4]; s = v.x + v.y + v.z + v.w; }
#pragma unroll
    for (int d = 16; d > 0; d >>= 1) s += __shfl_down_sync(0xffffffffu, s, d);
    __shared__ int wt[8];
    if ((tid & 31) == 0) wt[tid >> 5] = s;
    __syncthreads();
    if (tid < 8) {
        int v = wt[tid];
#pragma unroll
        for (int d = 4; d > 0; d >>= 1) v += __shfl_down_sync(0xffu, v, d);
        if (tid == 0) part[dir * NBLK + b] = v;
    }
}
__global__ void scan_part(int* __restrict__ part, int* __restrict__ off_td,
                          int* __restrict__ off_bu) {
    int w = threadIdx.x >> 5, lane = threadIdx.x & 31;
    if (w >= 2) return;
    int* p = part + w * NBLK;
    int v0 = (lane < NBLK) ? p[lane] : 0;
    int v1 = (lane + 32 < NBLK) ? p[lane + 32] : 0;
    int s0 = v0;
#pragma unroll
    for (int d = 1; d < 32; d <<= 1) {
        int t = __shfl_up_sync(0xffffffffu, s0, d);
        if (lane >= d) s0 += t;
    }
    int tot0 = __shfl_sync(0xffffffffu, s0, 31);
    int s1 = v1;
#pragma unroll
    for (int d = 1; d < 32; d <<= 1) {
        int t = __shfl_up_sync(0xffffffffu, s1, d);
        if (lane >= d) s1 += t;
    }
    s1 += tot0;
    if (lane < NBLK) p[lane] = s0 - v0;
    if (lane + 32 < NBLK) p[lane + 32] = s1 - v1;
    int total = __shfl_sync(0xffffffffu, s1, 31);
    if (lane == 0) (w == 0 ? off_td : off_bu)[NN] = total;
}
__global__ void scan_write(const int* __restrict__ deg, const int* __restrict__ part,
                           int* __restrict__ off_td, int* __restrict__ off_bu,
                           int* __restrict__ cur_td, int* __restrict__ cur_bu) {
    int dir = blockIdx.y, b = blockIdx.x, tid = threadIdx.x;
    int lane = tid & 31, w = tid >> 5;
    const int4* d4 = (const int4*)(deg + dir * NN);
    int i4 = b * 256 + tid;
    int4 v = make_int4(0, 0, 0, 0);
    if (i4 < N4) v = d4[i4];
    int ts = v.x + v.y + v.z + v.w;
    int incl = ts;
#pragma unroll
    for (int d = 1; d < 32; d <<= 1) {
        int t = __shfl_up_sync(0xffffffffu, incl, d);
        if (lane >= d) incl += t;
    }
    __shared__ int wt[8];
    if (lane == 31) wt[w] = incl;
    __syncthreads();
    if (w == 0 && lane < 8) {
        int x = wt[lane];
        int sx = x;
#pragma unroll
        for (int d = 1; d < 8; d <<= 1) {
            int t = __shfl_up_sync(0xffu, sx, d);
            if (lane >= d) sx += t;
        }
        wt[lane] = sx - x;
    }
    __syncthreads();
    int base = part[dir * NBLK + b] + wt[w] + (incl - ts);
    int* off = dir ? off_bu : off_td;
    int* cur = dir ? cur_bu : cur_td;
    if (i4 < N4) {
        int4 o;
        o.x = base;
        o.y = base + v.x;
        o.z = o.y + v.y;
        o.w = o.z + v.z;
        ((int4*)off)[i4] = o;
        ((int4*)cur)[i4] = o;
    }
}
__global__ void scatter_kernel(const int* __restrict__ src, const int* __restrict__ dst,
                               int* cur_td, int* cur_bu,
                               int* __restrict__ csr_td, int* __restrict__ csr_bu, int e) {
    int i = blockIdx.x * blockDim.x + threadIdx.x;
    if (i < e) {
        int s = src[i], d = dst[i];
        csr_td[atomicAdd(&cur_td[d], 1)] = s;
        csr_bu[atomicAdd(&cur_bu[s], 1)] = d;
    }
}

// ---------------- fp16 pipelined GEMM (cp.async, BK=32, double-buffered) ----------
#define AH_HALVES (128 * 40)
__global__ __launch_bounds__(256, 2)
void gemm_h(const __half* __restrict__ A0, const __half* __restrict__ A1,
            const __half* __restrict__ B0, const __half* __restrict__ B1,
            const float* __restrict__ rs0, const float* __restrict__ rs1,
            __half* __restrict__ C0, __half* __restrict__ C1,
            int M, int K, int lda, int ldc) {
    __shared__ __align__(16) __half As[2][AH_HALVES];
    __shared__ __align__(16) __half Bs[2][AH_HALVES];

    const __half* A = blockIdx.y ? A1 : A0;
    const __half* B = blockIdx.y ? B1 : B0;
    const float* rowscale = blockIdx.y ? rs1 : rs0;
    __half* C = blockIdx.y ? C1 : C0;

    const int tid = threadIdx.x;
    const int lane = tid & 31;
    const int warp = tid >> 5;
    const int g = lane >> 2, tig = lane & 3;
    const int m0 = blockIdx.x * 128;
    const int wm = (warp & 1) * 64, wn = (warp >> 1) * 32;

    const uint32_t sA = (uint32_t)__cvta_generic_to_shared(&As[0][0]);
    const uint32_t sB = (uint32_t)__cvta_generic_to_shared(&Bs[0][0]);

    float acc[4][4][4];
#pragma unroll
    for (int i = 0; i < 4; i++)
#pragma unroll
        for (int j = 0; j < 4; j++)
#pragma unroll
            for (int c = 0; c < 4; c++) acc[i][j][c] = 0.f;

    const int T = K >> 5;

#define ISSUEH(t)                                                                   \
    {                                                                               \
        const int k0 = (t) * 32;                                                    \
        const uint32_t ab = sA + (uint32_t)(((t) & 1) * AH_HALVES * 2);             \
        const uint32_t bb = sB + (uint32_t)(((t) & 1) * AH_HALVES * 2);             \
        _Pragma("unroll")                                                           \
        for (int l = 0; l < 2; l++) {                                               \
            int idx = tid + l * 256;                                                \
            int row = idx >> 2, ck = idx & 3;                                       \
            int gm = m0 + row;                                                      \
            const __half* srcp = A + (size_t)(gm < M ? gm : 0) * lda + k0 + ck * 8; \
            uint32_t dstp = ab + (uint32_t)(row * 80 + ck * 16);                    \
            int sz = gm < M ? 16 : 0;                                               \
            asm volatile("cp.async.cg.shared.global [%0], [%1], 16, %2;"            \
                         :: "r"(dstp), "l"(srcp), "r"(sz));                         \
        }                                                                           \
        _Pragma("unroll")                                                           \
        for (int l = 0; l < 2; l++) {                                               \
            int idx = tid + l * 256;                                                \
            int nr = idx >> 2, ck = idx & 3;                                        \
            const __half* srcp = B + (size_t)nr * K + k0 + ck * 8;                  \
            uint32_t dstp = bb + (uint32_t)(nr * 80 + ck * 16);                     \
            asm volatile("cp.async.cg.shared.global [%0], [%1], 16;"                \
                         :: "r"(dstp), "l"(srcp));                                  \
        }                                                                           \
        asm volatile("cp.async.commit_group;");                                     \
    }

    ISSUEH(0);
    for (int t = 0; t < T; t++) {
        if (t + 1 < T) {
            ISSUEH(t + 1);
            asm volatile("cp.async.wait_group 1;");
        } else {
            asm volatile("cp.async.wait_group 0;");
        }
        __syncthreads();
        const uint32_t* Aw = (const uint32_t*)&As[t & 1][0];
        const uint32_t* Bw = (const uint32_t*)&Bs[t & 1][0];
#pragma unroll
        for (int kk = 0; kk < 32; kk += 16) {
            const int kw = kk >> 1;
            uint32_t af[4][4], bf[4][2];
#pragma unroll
            for (int i = 0; i < 4; i++) {
                int mb = wm + i * 16 + g;
                af[i][0] = Aw[mb * 20 + kw + tig];
                af[i][1] = Aw[(mb + 8) * 20 + kw + tig];
                af[i][2] = Aw[mb * 20 + kw + 4 + tig];
                af[i][3] = Aw[(mb + 8) * 20 + kw + 4 + tig];
            }
#pragma unroll
            for (int j = 0; j < 4; j++) {
                int nb = wn + j * 8 + g;
                bf[j][0] = Bw[nb * 20 + kw + tig];
                bf[j][1] = Bw[nb * 20 + kw + 4 + tig];
            }
#pragma unroll
            for (int i = 0; i < 4; i++)
#pragma unroll
                for (int j = 0; j < 4; j++) {
                    asm volatile(
                        "mma.sync.aligned.m16n8k16.row.col.f32.f16.f16.f32 "
                        "{%0,%1,%2,%3}, {%4,%5,%6,%7}, {%8,%9}, {%0,%1,%2,%3};"
                        : "+f"(acc[i][j][0]), "+f"(acc[i][j][1]),
                          "+f"(acc[i][j][2]), "+f"(acc[i][j][3])
                        : "r"(af[i][0]), "r"(af[i][1]), "r"(af[i][2]), "r"(af[i][3]),
                          "r"(bf[j][0]), "r"(bf[j][1]));
                }
        }
        __syncthreads();
    }
#undef ISSUEH

#pragma unroll
    for (int i = 0; i < 4; i++) {
        int r0 = m0 + wm + i * 16 + g;
        int r1 = r0 + 8;
        float s0 = (r0 < M) ? rowscale[r0] : 1.f;
        float s1 = (r1 < M) ? rowscale[r1] : 1.f;
#pragma unroll
        for (int j = 0; j < 4; j++) {
            int cb = wn + j * 8 + 2 * tig;
            if (r0 < M) {
                __half2 p = __floats2half2_rn(acc[i][j][0] * s0, acc[i][j][1] * s0);
                *(__half2*)(C + (size_t)r0 * ldc + cb) = p;
            }
            if (r1 < M) {
                __half2 p = __floats2half2_rn(acc[i][j][2] * s1, acc[i][j][3] * s1);
                *(__half2*)(C + (size_t)r1 * ldc + cb) = p;
            }
        }
    }
}

// ---------------- small TF32 GEMM for MLP head (proven) ----------------
__device__ __forceinline__ uint32_t f2tf(float x) {
    uint32_t r;
    asm("cvt.rna.tf32.f32 %0, %1;" : "=r"(r) : "f"(x));
    return r;
}
__global__ __launch_bounds__(256, 2)
void gemm_tf32(const float* __restrict__ A, const float* __restrict__ B,
               const float* __restrict__ bias, float* __restrict__ C,
               int M, int K, int ldb, int ldc, int relu) {
    __shared__ uint32_t As[32][136];
    __shared__ uint32_t Bs[32][136];

    const int tid = threadIdx.x;
    const int lane = tid & 31;
    const int warp = tid >> 5;
    const int g = lane >> 2, tig = lane & 3;
    const int m0 = blockIdx.x * 128, n0 = blockIdx.y * 128;
    const int wm = (warp & 1) * 64, wn = (warp >> 1) * 32;

    float acc[4][4][4];
#pragma unroll
    for (int i = 0; i < 4; i++)
#pragma unroll
        for (int j = 0; j < 4; j++)
#pragma unroll
            for (int c = 0; c < 4; c++) acc[i][j][c] = 0.f;

    for (int k0 = 0; k0 < K; k0 += 32) {
#pragma unroll
        for (int r = 0; r < 4; r++) {
            int m = lane + 32 * r;
            int gm = m0 + m;
            float4 v = make_float4(0.f, 0.f, 0.f, 0.f);
            if (gm < M) v = *(const float4*)(A + (size_t)gm * K + k0 + warp * 4);
            As[warp * 4 + 0][m] = f2tf(v.x);
            As[warp * 4 + 1][m] = f2tf(v.y);
            As[warp * 4 + 2][m] = f2tf(v.z);
            As[warp * 4 + 3][m] = f2tf(v.w);
        }
#pragma unroll
        for (int l = 0; l < 4; l++) {
            int idx = tid + l * 256;
            int k = idx >> 5, nf = idx & 31;
            float4 v = *(const float4*)(B + (size_t)(k0 + k) * ldb + n0 + nf * 4);
            uint32_t* p = &Bs[k][nf * 4];
            p[0] = f2tf(v.x); p[1] = f2tf(v.y); p[2] = f2tf(v.z); p[3] = f2tf(v.w);
        }
        __syncthreads();
#pragma unroll
        for (int kk = 0; kk < 32; kk += 8) {
            uint32_t af[4][4], bf[4][2];
#pragma unroll
            for (int i = 0; i < 4; i++) {
                int mb = wm + i * 16 + g;
                af[i][0] = As[kk + tig][mb];
                af[i][1] = As[kk + tig][mb + 8];
                af[i][2] = As[kk + tig + 4][mb];
                af[i][3] = As[kk + tig + 4][mb + 8];
            }
#pragma unroll
            for (int j = 0; j < 4; j++) {
                int nb = wn + j * 8 + g;
                bf[j][0] = Bs[kk + tig][nb];
                bf[j][1] = Bs[kk + tig + 4][nb];
            }
#pragma unroll
            for (int i = 0; i < 4; i++)
#pragma unroll
                for (int j = 0; j < 4; j++) {
                    asm volatile(
                        "mma.sync.aligned.m16n8k8.row.col.f32.tf32.tf32.f32 "
                        "{%0,%1,%2,%3}, {%4,%5,%6,%7}, {%8,%9}, {%0,%1,%2,%3};"
                        : "+f"(acc[i][j][0]), "+f"(acc[i][j][1]),
                          "+f"(acc[i][j][2]), "+f"(acc[i][j][3])
                        : "r"(af[i][0]), "r"(af[i][1]), "r"(af[i][2]), "r"(af[i][3]),
                          "r"(bf[j][0]), "r"(bf[j][1]));
                }
        }
        __syncthreads();
    }

#pragma unroll
    for (int i = 0; i < 4; i++) {
        int r0 = m0 + wm + i * 16 + g;
        int r1 = r0 + 8;
#pragma unroll
        for (int j = 0; j < 4; j++) {
            int cb = n0 + wn + j * 8 + 2 * tig;
            float b0 = 0.f, b1 = 0.f;
            if (bias) { b0 = bias[cb]; b1 = bias[cb + 1]; }
            float v0 = acc[i][j][0] + b0, v1 = acc[i][j][1] + b1;
            float v2 = acc[i][j][2] + b0, v3 = acc[i][j][3] + b1;
            if (relu) {
                v0 = fmaxf(v0, 0.f); v1 = fmaxf(v1, 0.f);
                v2 = fmaxf(v2, 0.f); v3 = fmaxf(v3, 0.f);
            }
            if (r0 < M) *(float2*)(C + (size_t)r0 * ldc + cb) = make_float2(v0, v1);
            if (r1 < M) *(float2*)(C + (size_t)r1 * ldc + cb) = make_float2(v2, v3);
        }
    }
}

// ---------------- dual CSR aggregation (R10 shape + unroll-4 index prefetch) ------
// h prescaled by dinv. out = act( dinv[d]*(Σ h'[s] + h'[d]) + b )
// One warp per (node, direction); lane covers 4 halves (uint2 = 8 B).
__global__ void agg_dual_h(const __half* __restrict__ h,
                           const int* __restrict__ csr0, const int* __restrict__ csr1,
                           const int* __restrict__ off0, const int* __restrict__ off1,
                           const float* __restrict__ dv0, const float* __restrict__ dv1,
                           const float* __restrict__ b0, const float* __restrict__ b1,
                           __half* __restrict__ out0, __half* __restrict__ out1, int relu,
                           const int* __restrict__ batch, float* __restrict__ pool) {
    const int y = blockIdx.y;
    const int* csr = y ? csr1 : csr0;
    const int* off = y ? off1 : off0;
    const float* dinv = y ? dv1 : dv0;
    const float* bias = y ? b1 : b0;
    __half* out = y ? out1 : out0;
    const int ho = y * 128;

    int node = (blockIdx.x * blockDim.x + threadIdx.x) >> 5;
    if (node >= NN) return;
    int lane = threadIdx.x & 31;
    const __half* hp = h + ho + lane * 4;          // + s*256 per row

    int e0 = off[node], e1 = off[node + 1];
    float4 acc = make_float4(0.f, 0.f, 0.f, 0.f);
    int j = e0;
    for (; j + 4 <= e1; j += 4) {
        // 4 warp-uniform index loads, then 4 independent gathers in flight
        int s0 = csr[j], s1 = csr[j + 1], s2 = csr[j + 2], s3 = csr[j + 3];
        uint2 v0 = *(const uint2*)(hp + (size_t)s0 * 256);
        uint2 v1 = *(const uint2*)(hp + (size_t)s1 * 256);
        uint2 v2 = *(const uint2*)(hp + (size_t)s2 * 256);
        uint2 v3 = *(const uint2*)(hp + (size_t)s3 * 256);
        float2 a0 = __half22float2(*(__half2*)&v0.x), a1 = __half22float2(*(__half2*)&v0.y);
        float2 c0 = __half22float2(*(__half2*)&v1.x), c1 = __half22float2(*(__half2*)&v1.y);
        float2 d0 = __half22float2(*(__half2*)&v2.x), d1 = __half22float2(*(__half2*)&v2.y);
        float2 e0f = __half22float2(*(__half2*)&v3.x), e1f = __half22float2(*(__half2*)&v3.y);
        acc.x += (a0.x + c0.x) + (d0.x + e0f.x);
        acc.y += (a0.y + c0.y) + (d0.y + e0f.y);
        acc.z += (a1.x + c1.x) + (d1.x + e1f.x);
        acc.w += (a1.y + c1.y) + (d1.y + e1f.y);
    }
    for (; j < e1; j++) {
        int s = csr[j];
        uint2 v = *(const uint2*)(hp + (size_t)s * 256);
        float2 f0 = __half22float2(*(__half2*)&v.x);
        float2 f1 = __half22float2(*(__half2*)&v.y);
        acc.x += f0.x; acc.y += f0.y; acc.z += f1.x; acc.w += f1.y;
    }
    float di = dinv[node];
    uint2 sv2 = *(const uint2*)(hp + (size_t)node * 256);
    float2 s0f = __half22float2(*(__half2*)&sv2.x);
    float2 s1f = __half22float2(*(__half2*)&sv2.y);
    float4 bv = *(const float4*)(bias + lane * 4);
    float4 r;
    r.x = fmaf(di, acc.x + s0f.x, bv.x);
    r.y = fmaf(di, acc.y + s0f.y, bv.y);
    r.z = fmaf(di, acc.z + s1f.x, bv.z);
    r.w = fmaf(di, acc.w + s1f.y, bv.w);
    if (relu) {
        r.x = fmaxf(r.x, 0.f); r.y = fmaxf(r.y, 0.f);
        r.z = fmaxf(r.z, 0.f); r.w = fmaxf(r.w, 0.f);
    }
    if (pool) {
        int gi = batch[node];
        int po = y ? 0 : 128;           // td -> cols [128,256), bu -> [0,128)
        float* p = pool + (size_t)gi * 256 + po + lane * 4;
        atomicAdd(p + 0, r.x);
        atomicAdd(p + 1, r.y);
        atomicAdd(p + 2, r.z);
        atomicAdd(p + 3, r.w);
    } else {
        __half2 o0 = __floats2half2_rn(r.x, r.y);
        __half2 o1 = __floats2half2_rn(r.z, r.w);
        uint2 o;
        o.x = *(uint32_t*)&o0; o.y = *(uint32_t*)&o1;
        *(uint2*)(out + (size_t)node * 128 + lane * 4) = o;
    }
}

// ---------------- launch ----------------
extern "C" void kernel_launch(void* const* d_in, const int* in_sizes, int n_in,
                              void* d_out, int out_size) {
    const float* x     = (const float*)d_in[0];
    const int*   ei    = (const int*)d_in[1];
    const int*   batch = (const int*)d_in[2];
    const float* td_W1 = (const float*)d_in[4];
    const float* td_b1 = (const float*)d_in[5];
    const float* td_W2 = (const float*)d_in[6];
    const float* td_b2 = (const float*)d_in[7];
    const float* bu_W1 = (const float*)d_in[8];
    const float* bu_b1 = (const float*)d_in[9];
    const float* bu_W2 = (const float*)d_in[10];
    const float* bu_b2 = (const float*)d_in[11];
    const float* pw1   = (const float*)d_in[12];
    const float* pb1   = (const float*)d_in[13];
    const float* pw2   = (const float*)d_in[14];
    const float* pb2   = (const float*)d_in[15];
    float* out = (float*)d_out;

    __half *xh, *bufh, *h1td, *h1bu, *wt1, *wt2;
    float *pool, *mlp, *dinv;
    int *deg, *off_td, *off_bu, *cur_td, *cur_bu, *part, *csr_td, *csr_bu;
    cudaGetSymbolAddress((void**)&xh,     g_xh);
    cudaGetSymbolAddress((void**)&bufh,   g_bufh);
    cudaGetSymbolAddress((void**)&h1td,   g_h1td);
    cudaGetSymbolAddress((void**)&h1bu,   g_h1bu);
    cudaGetSymbolAddress((void**)&wt1,    g_wt1);
    cudaGetSymbolAddress((void**)&wt2,    g_wt2);
    cudaGetSymbolAddress((void**)&pool,   g_pool);
    cudaGetSymbolAddress((void**)&mlp,    g_mlp);
    cudaGetSymbolAddress((void**)&dinv,   g_dinv);
    cudaGetSymbolAddress((void**)&deg,    g_deg);
    cudaGetSymbolAddress((void**)&off_td, g_off_td);
    cudaGetSymbolAddress((void**)&off_bu, g_off_bu);
    cudaGetSymbolAddress((void**)&cur_td, g_cur_td);
    cudaGetSymbolAddress((void**)&cur_bu, g_cur_bu);
    cudaGetSymbolAddress((void**)&part,   g_part);
    cudaGetSymbolAddress((void**)&csr_td, g_csr_td);
    cudaGetSymbolAddress((void**)&csr_bu, g_csr_bu);

    const int* src = ei;
    const int* dst = ei + EE;
    const float* dinv_td = dinv;
    const float* dinv_bu = dinv + NN;

    // --- graph structure ---
    zero_i<<<(2 * NN + 255) / 256, 256>>>(deg, 2 * NN);
    deg_kernel<<<(EE + 255) / 256, 256>>>(src, dst, deg, deg + NN, EE);
    dinv_kernel<<<(2 * NN + 255) / 256, 256>>>(deg, dinv, 2 * NN);
    scan_bsum<<<dim3(NBLK, 2), 256>>>(deg, part);
    scan_part<<<1, 64>>>(part, off_td, off_bu);
    scan_write<<<dim3(NBLK, 2), 256>>>(deg, part, off_td, off_bu, cur_td, cur_bu);
    scatter_kernel<<<(EE + 255) / 256, 256>>>(src, dst, cur_td, cur_bu, csr_td, csr_bu, EE);

    // --- converts + pool zero ---
    cvt_x<<<(NN * 32 + 255) / 256, 256>>>(x, xh, NN * 32);
    cvt_w<<<(256 * 256 + 256 * 128 + 255) / 256, 256>>>(td_W1, bu_W1, td_W2, bu_W2, wt1, wt2);
    zero_f4<<<(NG * 64 + 255) / 256, 256>>>(pool, NG * 64);

    const int gx = (NN + 127) / 128;                 // 391
    const int aggBlocks = (NN * 32 + 255) / 256;     // one warp per node

    // conv1 GEMM (both branches): bufh = (xh @ W1^T) * dinv
    gemm_h<<<dim3(gx, 2), 256>>>(xh, xh, wt1, wt1 + 128 * 256, dinv_td, dinv_bu,
                                 bufh, bufh + 128, NN, 256, 256, 256);

    // conv1 aggregation + bias + relu -> h1 (fp16)
    agg_dual_h<<<dim3(aggBlocks, 2), 256>>>(bufh, csr_td, csr_bu, off_td, off_bu,
                                            dinv_td, dinv_bu, td_b1, bu_b1,
                                            h1td, h1bu, 1, nullptr, nullptr);

    // conv2 GEMMs (both branches, prescaled)
    gemm_h<<<dim3(gx, 2), 256>>>(h1td, h1bu, wt2, wt2 + 128 * 128, dinv_td, dinv_bu,
                                 bufh, bufh + 128, NN, 128, 128, 256);

    // conv2 aggregation + bias, pooled into concat buffer [bu | td] (fp32)
    agg_dual_h<<<dim3(aggBlocks, 2), 256>>>(bufh, csr_td, csr_bu, off_td, off_bu,
                                            dinv_td, dinv_bu, td_b2, bu_b2,
                                            nullptr, nullptr, 0, batch, pool);

    // MLP head (fp32 tf32 path)
    gemm_tf32<<<dim3(4, 2), 256>>>(pool, pw1, pb1, mlp, NG, 256, 256, 256, 1);
    gemm_tf32<<<dim3(4, 1), 256>>>(mlp,  pw2, pb2, out, NG, 256, 128, 128, 0);
}